// round 1
// baseline (speedup 1.0000x reference)
#include <cuda_runtime.h>
#include <math.h>

// ---------------- Problem constants ----------------
#define B_    32
#define T_    512
#define C_    32
#define D_    512
#define H_    8
#define E_    64
#define DFF_  2048
#define NL_   3
#define P_    16
#define N_    64
#define BC_   (B_*C_)          // 1024
#define ROWS_ ((BC_)*(N_))     // 65536

// ---------------- Scratch (device globals; no allocation) ----------------
__device__ float g_mean[BC_];
__device__ float g_std[BC_];
__device__ float g_tok [ROWS_ * D_];
__device__ float g_q   [ROWS_ * D_];
__device__ float g_k   [ROWS_ * D_];
__device__ float g_v   [ROWS_ * D_];
__device__ float g_attn[ROWS_ * D_];
__device__ float g_y   [ROWS_ * D_];
__device__ float g_h   [ROWS_ * DFF_];
__device__ float g_enc [BC_ * (D_ * N_)];
__device__ float g_psum[256 * D_];
__device__ float g_psq [256 * D_];
__device__ float g_bna [D_];
__device__ float g_bnb [D_];

// ---------------- Instance-norm stats over time ----------------
__global__ void inst_stats_kernel(const float* __restrict__ x_enc) {
    int bc = blockIdx.x;            // b*32 + c
    int b = bc >> 5, c = bc & 31;
    int tid = threadIdx.x;          // 256
    const float* p = x_enc + (size_t)b * T_ * C_ + c;
    float v0 = p[(size_t)tid * C_];
    float v1 = p[(size_t)(tid + 256) * C_];
    float s = v0 + v1, q = v0 * v0 + v1 * v1;
    __shared__ float rs[256], rq[256];
    rs[tid] = s; rq[tid] = q;
    __syncthreads();
    for (int off = 128; off > 0; off >>= 1) {
        if (tid < off) { rs[tid] += rs[tid + off]; rq[tid] += rq[tid + off]; }
        __syncthreads();
    }
    if (tid == 0) {
        float mean = rs[0] / (float)T_;
        float var  = rq[0] / (float)T_ - mean * mean;
        g_mean[bc] = mean;
        g_std[bc]  = sqrtf(var + 1e-5f);
    }
}

// ---------------- Patch embedding + sinusoidal PE ----------------
__global__ void patch_embed_kernel(const float* __restrict__ x_enc,
                                   const float* __restrict__ W_val) {
    int bn = blockIdx.x;            // bc*64 + n
    int bc = bn >> 6, n = bn & 63;
    int b = bc >> 5, c = bc & 31;
    int d = threadIdx.x;            // 512
    __shared__ float pv[P_];
    if (d < P_) {
        int t = n * 8 + d;
        if (t > T_ - 1) t = T_ - 1;      // replication pad
        pv[d] = (x_enc[(size_t)(b * T_ + t) * C_ + c] - g_mean[bc]) / g_std[bc];
    }
    __syncthreads();
    // positional encoding
    int i2 = d >> 1;
    float div = expf(-(float)(2 * i2) * (logf(10000.0f) / (float)D_));
    float ang = (float)n * div;
    float acc = (d & 1) ? cosf(ang) : sinf(ang);
    #pragma unroll
    for (int p = 0; p < P_; p++)
        acc = fmaf(pv[p], W_val[p * D_ + d], acc);
    g_tok[(size_t)bn * D_ + d] = acc;
}

// ---------------- Tiled fp32 GEMM with fused epilogues ----------------
// EPI 0: C = A*B + bias
// EPI 1: C = A*B + bias + res
// EPI 2: C = gelu_exact(A*B + bias)
// EPI 3: head: out[b,t,c] = (A*B + bias)*std + mean (scatter, denorm)
#define GBM 128
#define GBN 128
#define GBK 8

template<int EPI>
__global__ __launch_bounds__(256, 2)
void sgemm_kernel(const float* __restrict__ A, const float* __restrict__ B,
                  const float* __restrict__ bias, const float* __restrict__ res,
                  float* __restrict__ C, int M, int N, int K) {
    __shared__ float As[GBK][GBM];
    __shared__ float Bs[GBK][GBN];
    int tid = threadIdx.x;
    int bm = blockIdx.y * GBM;
    int bn = blockIdx.x * GBN;
    int tx = tid & 15, ty = tid >> 4;
    int tm = ty * 8, tn = tx * 8;

    float acc[8][8];
    #pragma unroll
    for (int i = 0; i < 8; i++)
        #pragma unroll
        for (int j = 0; j < 8; j++) acc[i][j] = 0.0f;

    int arow = tid >> 1;
    int acol = (tid & 1) * 4;
    int brow = tid >> 5;
    int bcol = (tid & 31) * 4;

    const float* Aptr = A + (size_t)(bm + arow) * K + acol;
    const float* Bptr = B + (size_t)brow * N + bn + bcol;

    for (int k0 = 0; k0 < K; k0 += GBK) {
        float4 a4 = *(const float4*)(Aptr + k0);
        float4 b4 = *(const float4*)(Bptr + (size_t)k0 * N);
        As[acol + 0][arow] = a4.x;
        As[acol + 1][arow] = a4.y;
        As[acol + 2][arow] = a4.z;
        As[acol + 3][arow] = a4.w;
        *(float4*)&Bs[brow][bcol] = b4;
        __syncthreads();
        #pragma unroll
        for (int kk = 0; kk < GBK; kk++) {
            float ra[8], rb[8];
            *(float4*)&ra[0] = *(const float4*)&As[kk][tm];
            *(float4*)&ra[4] = *(const float4*)&As[kk][tm + 4];
            *(float4*)&rb[0] = *(const float4*)&Bs[kk][tn];
            *(float4*)&rb[4] = *(const float4*)&Bs[kk][tn + 4];
            #pragma unroll
            for (int i = 0; i < 8; i++)
                #pragma unroll
                for (int j = 0; j < 8; j++)
                    acc[i][j] = fmaf(ra[i], rb[j], acc[i][j]);
        }
        __syncthreads();
    }

    #pragma unroll
    for (int i = 0; i < 8; i++) {
        int m = bm + tm + i;
        #pragma unroll
        for (int j = 0; j < 8; j++) {
            int col = bn + tn + j;
            float v = acc[i][j] + bias[col];
            if (EPI == 1) v += res[(size_t)m * N + col];
            if (EPI == 2) v = 0.5f * v * (1.0f + erff(v * 0.70710678118654752f));
            if (EPI == 3) {
                // m = bc (b*32+c), col = t; out[b,t,c]
                int bb = m >> 5, cc = m & 31;
                C[((size_t)bb * T_ + col) * C_ + cc] = v * g_std[m] + g_mean[m];
            } else {
                C[(size_t)m * N + col] = v;
            }
        }
    }
}

// ---------------- Attention (per bc, per head) ----------------
#define ATTN_SMEM (4 * 64 * 65 * 4)
__global__ void attn_kernel() {
    int bh = blockIdx.x;
    int bc = bh >> 3, h = bh & 7;
    extern __shared__ float sm[];
    float* qs = sm;
    float* ks = qs + 64 * 65;
    float* vs = ks + 64 * 65;
    float* ss = vs + 64 * 65;
    int tid = threadIdx.x;   // 256
    const float* Qb = g_q + (size_t)bc * 64 * D_ + h * 64;
    const float* Kb = g_k + (size_t)bc * 64 * D_ + h * 64;
    const float* Vb = g_v + (size_t)bc * 64 * D_ + h * 64;

    #pragma unroll
    for (int i = 0; i < 16; i++) {
        int flat = i * 256 + tid;
        int l = flat >> 6, e = flat & 63;
        qs[l * 65 + e] = Qb[(size_t)l * D_ + e];
        ks[l * 65 + e] = Kb[(size_t)l * D_ + e];
        vs[l * 65 + e] = Vb[(size_t)l * D_ + e];
    }
    __syncthreads();

    #pragma unroll
    for (int i = 0; i < 16; i++) {
        int flat = i * 256 + tid;
        int l = flat >> 6, s = flat & 63;
        float acc = 0.0f;
        #pragma unroll
        for (int e = 0; e < 64; e++)
            acc = fmaf(qs[l * 65 + e], ks[s * 65 + e], acc);
        ss[l * 65 + s] = acc * 0.125f;   // 1/sqrt(64)
    }
    __syncthreads();

    if (tid < 64) {
        int l = tid;
        float mx = -1e30f;
        #pragma unroll
        for (int s = 0; s < 64; s++) mx = fmaxf(mx, ss[l * 65 + s]);
        float sum = 0.0f;
        #pragma unroll
        for (int s = 0; s < 64; s++) {
            float e = expf(ss[l * 65 + s] - mx);
            ss[l * 65 + s] = e;
            sum += e;
        }
        float inv = 1.0f / sum;
        #pragma unroll
        for (int s = 0; s < 64; s++) ss[l * 65 + s] *= inv;
    }
    __syncthreads();

    #pragma unroll
    for (int i = 0; i < 16; i++) {
        int flat = i * 256 + tid;
        int l = flat >> 6, e = flat & 63;
        float acc = 0.0f;
        #pragma unroll
        for (int s = 0; s < 64; s++)
            acc = fmaf(ss[l * 65 + s], vs[s * 65 + e], acc);
        g_attn[((size_t)bc * 64 + l) * D_ + h * 64 + e] = acc;
    }
}

// ---------------- LayerNorm (row of 512) ----------------
__global__ void ln_kernel(const float* __restrict__ X,
                          const float* __restrict__ g, const float* __restrict__ b,
                          float* __restrict__ Y) {
    int row = blockIdx.x;
    int tid = threadIdx.x;  // 256
    const float* x = X + (size_t)row * D_;
    float v0 = x[tid], v1 = x[tid + 256];
    __shared__ float rs[256], rq[256];
    rs[tid] = v0 + v1;
    rq[tid] = v0 * v0 + v1 * v1;
    __syncthreads();
    for (int off = 128; off > 0; off >>= 1) {
        if (tid < off) { rs[tid] += rs[tid + off]; rq[tid] += rq[tid + off]; }
        __syncthreads();
    }
    __shared__ float s_mean, s_inv;
    if (tid == 0) {
        float mean = rs[0] / (float)D_;
        float var  = rq[0] / (float)D_ - mean * mean;
        s_mean = mean;
        s_inv  = rsqrtf(var + 1e-5f);
    }
    __syncthreads();
    float mean = s_mean, inv = s_inv;
    Y[(size_t)row * D_ + tid]       = (v0 - mean) * inv * g[tid]       + b[tid];
    Y[(size_t)row * D_ + tid + 256] = (v1 - mean) * inv * g[tid + 256] + b[tid + 256];
}

// ---------------- BatchNorm stats (deterministic 2-stage) ----------------
__global__ void bn_partial_kernel() {
    int blk = blockIdx.x;     // 256 blocks * 256 rows
    int d = threadIdx.x;      // 512
    float s = 0.0f, q = 0.0f;
    const float* base = g_tok + (size_t)blk * 256 * D_ + d;
    for (int r = 0; r < 256; r++) {
        float v = base[(size_t)r * D_];
        s += v; q += v * v;
    }
    g_psum[blk * D_ + d] = s;
    g_psq [blk * D_ + d] = q;
}

__global__ void bn_final_kernel(const float* __restrict__ gam,
                                const float* __restrict__ bet) {
    int d = threadIdx.x;      // 512, one block
    float s = 0.0f, q = 0.0f;
    for (int i = 0; i < 256; i++) {
        s += g_psum[i * D_ + d];
        q += g_psq [i * D_ + d];
    }
    float mean = s / (float)ROWS_;
    float var  = q / (float)ROWS_ - mean * mean;
    float a = gam[d] * rsqrtf(var + 1e-5f);
    g_bna[d] = a;
    g_bnb[d] = bet[d] - mean * a;
}

// ---------------- BN apply + (N,D)->(D,N) transpose into enc ----------------
__global__ void enc_transpose_kernel() {
    __shared__ float sm[32][33];
    int bid = blockIdx.x;           // bc*32 + dt*2 + nt
    int bc = bid >> 5;
    int r = bid & 31;
    int dt = r >> 1, nt = r & 1;
    int tx = threadIdx.x, ty = threadIdx.y;   // 32 x 8
    int d0 = dt * 32, n0 = nt * 32;
    #pragma unroll
    for (int j = 0; j < 32; j += 8) {
        int n = n0 + ty + j;
        int d = d0 + tx;
        float v = g_tok[((size_t)bc * 64 + n) * D_ + d];
        sm[ty + j][tx] = v * g_bna[d] + g_bnb[d];
    }
    __syncthreads();
    #pragma unroll
    for (int j = 0; j < 32; j += 8) {
        int d = d0 + ty + j;
        int n = n0 + tx;
        g_enc[(size_t)bc * (D_ * N_) + d * N_ + n] = sm[tx][ty + j];
    }
}

// ---------------- Launch ----------------
extern "C" void kernel_launch(void* const* d_in, const int* in_sizes, int n_in,
                              void* d_out, int out_size) {
    const float* x_enc = (const float*)d_in[0];
    const float* W_val = (const float*)d_in[1];
    const float* Wq    = (const float*)d_in[2];
    const float* bq    = (const float*)d_in[3];
    const float* Wk    = (const float*)d_in[4];
    const float* bk    = (const float*)d_in[5];
    const float* Wv    = (const float*)d_in[6];
    const float* bv    = (const float*)d_in[7];
    const float* Wo    = (const float*)d_in[8];
    const float* bo    = (const float*)d_in[9];
    const float* Wc1   = (const float*)d_in[10];
    const float* bc1   = (const float*)d_in[11];
    const float* Wc2   = (const float*)d_in[12];
    const float* bc2   = (const float*)d_in[13];
    const float* ln1_g = (const float*)d_in[14];
    const float* ln1_b = (const float*)d_in[15];
    const float* ln2_g = (const float*)d_in[16];
    const float* ln2_b = (const float*)d_in[17];
    const float* bn_g  = (const float*)d_in[18];
    const float* bn_b  = (const float*)d_in[19];
    const float* W_head= (const float*)d_in[20];
    const float* b_head= (const float*)d_in[21];
    float* out = (float*)d_out;

    float *tok, *q, *k, *v, *attn, *y, *h, *enc;
    cudaGetSymbolAddress((void**)&tok,  g_tok);
    cudaGetSymbolAddress((void**)&q,    g_q);
    cudaGetSymbolAddress((void**)&k,    g_k);
    cudaGetSymbolAddress((void**)&v,    g_v);
    cudaGetSymbolAddress((void**)&attn, g_attn);
    cudaGetSymbolAddress((void**)&y,    g_y);
    cudaGetSymbolAddress((void**)&h,    g_h);
    cudaGetSymbolAddress((void**)&enc,  g_enc);

    cudaFuncSetAttribute(attn_kernel, cudaFuncAttributeMaxDynamicSharedMemorySize, ATTN_SMEM);

    inst_stats_kernel<<<BC_, 256>>>(x_enc);
    patch_embed_kernel<<<ROWS_, 512>>>(x_enc, W_val);

    dim3 gproj(D_ / GBN, ROWS_ / GBM);      // (4, 512)
    dim3 gff1(DFF_ / GBN, ROWS_ / GBM);     // (16, 512)
    dim3 ghead(T_ / GBN, BC_ / GBM);        // (4, 8)

    for (int i = 0; i < NL_; i++) {
        const float* Wq_i = Wq + (size_t)i * D_ * D_;
        const float* Wk_i = Wk + (size_t)i * D_ * D_;
        const float* Wv_i = Wv + (size_t)i * D_ * D_;
        const float* Wo_i = Wo + (size_t)i * D_ * D_;
        const float* Wc1_i = Wc1 + (size_t)i * D_ * DFF_;
        const float* Wc2_i = Wc2 + (size_t)i * DFF_ * D_;

        sgemm_kernel<0><<<gproj, 256>>>(tok, Wq_i, bq + i * D_, nullptr, q, ROWS_, D_, D_);
        sgemm_kernel<0><<<gproj, 256>>>(tok, Wk_i, bk + i * D_, nullptr, k, ROWS_, D_, D_);
        sgemm_kernel<0><<<gproj, 256>>>(tok, Wv_i, bv + i * D_, nullptr, v, ROWS_, D_, D_);
        attn_kernel<<<BC_ * H_, 256, ATTN_SMEM>>>();
        sgemm_kernel<1><<<gproj, 256>>>(attn, Wo_i, bo + i * D_, tok, tok, ROWS_, D_, D_);
        ln_kernel<<<ROWS_, 256>>>(tok, ln1_g + i * D_, ln1_b + i * D_, y);
        sgemm_kernel<2><<<gff1, 256>>>(y, Wc1_i, bc1 + i * DFF_, nullptr, h, ROWS_, DFF_, D_);
        sgemm_kernel<1><<<gproj, 256>>>(h, Wc2_i, bc2 + i * D_, tok, tok, ROWS_, D_, DFF_);
        ln_kernel<<<ROWS_, 256>>>(tok, ln2_g + i * D_, ln2_b + i * D_, tok);
    }

    bn_partial_kernel<<<256, 512>>>();
    bn_final_kernel<<<1, 512>>>(bn_g, bn_b);
    enc_transpose_kernel<<<BC_ * 32, dim3(32, 8)>>>();
    sgemm_kernel<3><<<ghead, 256>>>(enc, W_head, b_head, nullptr, out, BC_, T_, D_ * N_);
}

// round 2
// speedup vs baseline: 2.8332x; 2.8332x over previous
#include <cuda_runtime.h>
#include <math.h>
#include <stdint.h>

// ---------------- Problem constants ----------------
#define B_    32
#define T_    512
#define C_    32
#define D_    512
#define H_    8
#define E_    64
#define DFF_  2048
#define NL_   3
#define P_    16
#define N_    64
#define BC_   (B_*C_)          // 1024
#define ROWS_ ((BC_)*(N_))     // 65536
#define KSPLIT_ 4
#define KCH_    8192           // 32768 / 4

// ---------------- Scratch (device globals; no allocation) ----------------
__device__ float g_mean[BC_];
__device__ float g_std[BC_];
__device__ float g_tok [ROWS_ * D_];
__device__ float g_q   [ROWS_ * D_];
__device__ float g_k   [ROWS_ * D_];
__device__ float g_v   [ROWS_ * D_];
__device__ float g_attn[ROWS_ * D_];
__device__ float g_y   [ROWS_ * D_];
__device__ float g_h   [ROWS_ * DFF_];
__device__ float g_enc [BC_ * (D_ * N_)];
__device__ float g_hpart[KSPLIT_ * BC_ * T_];
__device__ float g_psum[256 * D_];
__device__ float g_psq [256 * D_];
__device__ float g_bna [D_];
__device__ float g_bnb [D_];

// ---------------- helpers ----------------
__device__ __forceinline__ uint32_t f2tf32(float f) {
    uint32_t u;
    asm("cvt.rna.tf32.f32 %0, %1;" : "=r"(u) : "f"(f));
    return u;
}

#define CP16(dst, src) asm volatile("cp.async.cg.shared.global [%0], [%1], 16;\n" :: "r"(dst), "l"(src))
#define CP_COMMIT()    asm volatile("cp.async.commit_group;\n")
#define CP_WAIT0()     asm volatile("cp.async.wait_group 0;\n")

// ---------------- Instance-norm stats over time ----------------
__global__ void inst_stats_kernel(const float* __restrict__ x_enc) {
    int bc = blockIdx.x;
    int b = bc >> 5, c = bc & 31;
    int tid = threadIdx.x;          // 256
    const float* p = x_enc + (size_t)b * T_ * C_ + c;
    float v0 = p[(size_t)tid * C_];
    float v1 = p[(size_t)(tid + 256) * C_];
    float s = v0 + v1, q = v0 * v0 + v1 * v1;
    __shared__ float rs[256], rq[256];
    rs[tid] = s; rq[tid] = q;
    __syncthreads();
    for (int off = 128; off > 0; off >>= 1) {
        if (tid < off) { rs[tid] += rs[tid + off]; rq[tid] += rq[tid + off]; }
        __syncthreads();
    }
    if (tid == 0) {
        float mean = rs[0] / (float)T_;
        float var  = rq[0] / (float)T_ - mean * mean;
        g_mean[bc] = mean;
        g_std[bc]  = sqrtf(var + 1e-5f);
    }
}

// ---------------- Patch embedding + sinusoidal PE ----------------
__global__ void patch_embed_kernel(const float* __restrict__ x_enc,
                                   const float* __restrict__ W_val) {
    int bn = blockIdx.x;            // bc*64 + n
    int bc = bn >> 6, n = bn & 63;
    int b = bc >> 5, c = bc & 31;
    int d = threadIdx.x;            // 512
    __shared__ float pv[P_];
    if (d < P_) {
        int t = n * 8 + d;
        if (t > T_ - 1) t = T_ - 1;
        pv[d] = (x_enc[(size_t)(b * T_ + t) * C_ + c] - g_mean[bc]) / g_std[bc];
    }
    __syncthreads();
    int i2 = d >> 1;
    float div = expf(-(float)(2 * i2) * (logf(10000.0f) / (float)D_));
    float ang = (float)n * div;
    float acc = (d & 1) ? cosf(ang) : sinf(ang);
    #pragma unroll
    for (int p = 0; p < P_; p++)
        acc = fmaf(pv[p], W_val[p * D_ + d], acc);
    g_tok[(size_t)bn * D_ + d] = acc;
}

// ---------------- TF32 tensor-core GEMM, 128x128x16 tiles ----------------
// EPI 0: C = A*B + bias
// EPI 1: C = A*B + bias + res
// EPI 2: C = gelu_exact(A*B + bias)
// EPI 4: C = A*B  (raw; split-K partial, blockIdx.z selects K chunk)
template<int EPI>
__global__ __launch_bounds__(256, 2)
void tgemm_kernel(const float* __restrict__ A, const float* __restrict__ B,
                  const float* __restrict__ bias, const float* __restrict__ res,
                  float* __restrict__ C, int M, int N, int K, int lda, int ldb) {
    __shared__ float As[2][128 * 20];    // [m][k], pitch 20 (conflict-free frag loads)
    __shared__ float Bs[2][16 * 132];    // [k][n], pitch 132

    if (EPI == 4) {
        size_t z = blockIdx.z;
        A += z * KCH_;                       // column offset within A row (lda=32768)
        B += z * (size_t)KCH_ * ldb;         // row offset in B
        C += z * (size_t)M * N;              // partial-output slab
    }

    const int tid  = threadIdx.x;
    const int warp = tid >> 5, lane = tid & 31;
    const int wm = warp >> 1, wn = warp & 1;       // 4x2 warp grid
    const int lr = lane >> 2, lc = lane & 3;
    const int bm = blockIdx.y * 128, bn = blockIdx.x * 128;

    float acc[2][8][4];
    #pragma unroll
    for (int mt = 0; mt < 2; mt++)
        #pragma unroll
        for (int nt = 0; nt < 8; nt++)
            #pragma unroll
            for (int i = 0; i < 4; i++) acc[mt][nt][i] = 0.0f;

    // per-thread copy assignments: 2 A-chunks + 2 B-chunks of 16B each
    const int qa0 = tid, qa1 = tid + 256;
    const int ar0 = qa0 >> 2, ac0 = (qa0 & 3) * 4;
    const int ar1 = qa1 >> 2, ac1 = (qa1 & 3) * 4;
    const int br0 = qa0 >> 5, bc0 = (qa0 & 31) * 4;
    const int br1 = qa1 >> 5, bc1 = (qa1 & 31) * 4;
    const float* pa0 = A + (size_t)(bm + ar0) * lda + ac0;
    const float* pa1 = A + (size_t)(bm + ar1) * lda + ac1;
    const float* pb0 = B + (size_t)br0 * ldb + bn + bc0;
    const float* pb1 = B + (size_t)br1 * ldb + bn + bc1;

    uint32_t sa0[2], sa1[2], sb0[2], sb1[2];
    #pragma unroll
    for (int s = 0; s < 2; s++) {
        sa0[s] = (uint32_t)__cvta_generic_to_shared(&As[s][ar0 * 20 + ac0]);
        sa1[s] = (uint32_t)__cvta_generic_to_shared(&As[s][ar1 * 20 + ac1]);
        sb0[s] = (uint32_t)__cvta_generic_to_shared(&Bs[s][br0 * 132 + bc0]);
        sb1[s] = (uint32_t)__cvta_generic_to_shared(&Bs[s][br1 * 132 + bc1]);
    }

    const int NIT = K >> 4;

    // prologue: stage 0
    {
        CP16(sa0[0], pa0);
        CP16(sa1[0], pa1);
        CP16(sb0[0], pb0);
        CP16(sb1[0], pb1);
        CP_COMMIT();
    }

    for (int it = 0; it < NIT; ++it) {
        CP_WAIT0();
        __syncthreads();
        if (it + 1 < NIT) {
            const int s2 = (it + 1) & 1;
            const int k0 = (it + 1) << 4;
            CP16(sa0[s2], pa0 + k0);
            CP16(sa1[s2], pa1 + k0);
            CP16(sb0[s2], pb0 + (size_t)k0 * ldb);
            CP16(sb1[s2], pb1 + (size_t)k0 * ldb);
            CP_COMMIT();
        }
        const int s = it & 1;
        #pragma unroll
        for (int ks = 0; ks < 2; ks++) {
            const int kb = ks * 8;
            uint32_t af[2][4];
            #pragma unroll
            for (int mt = 0; mt < 2; mt++) {
                int m0 = wm * 32 + mt * 16 + lr;
                af[mt][0] = f2tf32(As[s][(m0    ) * 20 + kb + lc    ]);
                af[mt][1] = f2tf32(As[s][(m0 + 8) * 20 + kb + lc    ]);
                af[mt][2] = f2tf32(As[s][(m0    ) * 20 + kb + lc + 4]);
                af[mt][3] = f2tf32(As[s][(m0 + 8) * 20 + kb + lc + 4]);
            }
            uint32_t bf[8][2];
            #pragma unroll
            for (int nt = 0; nt < 8; nt++) {
                int n0 = wn * 64 + nt * 8 + lr;
                bf[nt][0] = f2tf32(Bs[s][(kb + lc    ) * 132 + n0]);
                bf[nt][1] = f2tf32(Bs[s][(kb + lc + 4) * 132 + n0]);
            }
            #pragma unroll
            for (int mt = 0; mt < 2; mt++)
                #pragma unroll
                for (int nt = 0; nt < 8; nt++)
                    asm volatile(
                        "mma.sync.aligned.m16n8k8.row.col.f32.tf32.tf32.f32 "
                        "{%0,%1,%2,%3},{%4,%5,%6,%7},{%8,%9},{%0,%1,%2,%3};"
                        : "+f"(acc[mt][nt][0]), "+f"(acc[mt][nt][1]),
                          "+f"(acc[mt][nt][2]), "+f"(acc[mt][nt][3])
                        : "r"(af[mt][0]), "r"(af[mt][1]),
                          "r"(af[mt][2]), "r"(af[mt][3]),
                          "r"(bf[nt][0]), "r"(bf[nt][1]));
        }
        __syncthreads();
    }

    // ---------------- epilogue ----------------
    #pragma unroll
    for (int mt = 0; mt < 2; mt++) {
        #pragma unroll
        for (int half = 0; half < 2; half++) {       // row, row+8
            int m = bm + wm * 32 + mt * 16 + lr + half * 8;
            #pragma unroll
            for (int nt = 0; nt < 8; nt++) {
                int col = bn + wn * 64 + nt * 8 + lc * 2;
                float v0 = acc[mt][nt][half * 2 + 0];
                float v1 = acc[mt][nt][half * 2 + 1];
                if (EPI != 4) { v0 += bias[col]; v1 += bias[col + 1]; }
                if (EPI == 1) {
                    const float2 r2 = *(const float2*)(res + (size_t)m * N + col);
                    v0 += r2.x; v1 += r2.y;
                }
                if (EPI == 2) {
                    v0 = 0.5f * v0 * (1.0f + erff(v0 * 0.70710678118654752f));
                    v1 = 0.5f * v1 * (1.0f + erff(v1 * 0.70710678118654752f));
                }
                *(float2*)(C + (size_t)m * N + col) = make_float2(v0, v1);
            }
        }
    }
}

// ---------------- Attention (per bc, per head) ----------------
#define ATTN_SMEM (4 * 64 * 65 * 4)
__global__ void attn_kernel() {
    int bh = blockIdx.x;
    int bc = bh >> 3, h = bh & 7;
    extern __shared__ float sm[];
    float* qs = sm;
    float* ks = qs + 64 * 65;
    float* vs = ks + 64 * 65;
    float* ss = vs + 64 * 65;
    int tid = threadIdx.x;   // 256
    const float* Qb = g_q + (size_t)bc * 64 * D_ + h * 64;
    const float* Kb = g_k + (size_t)bc * 64 * D_ + h * 64;
    const float* Vb = g_v + (size_t)bc * 64 * D_ + h * 64;

    #pragma unroll
    for (int i = 0; i < 16; i++) {
        int flat = i * 256 + tid;
        int l = flat >> 6, e = flat & 63;
        qs[l * 65 + e] = Qb[(size_t)l * D_ + e];
        ks[l * 65 + e] = Kb[(size_t)l * D_ + e];
        vs[l * 65 + e] = Vb[(size_t)l * D_ + e];
    }
    __syncthreads();

    #pragma unroll
    for (int i = 0; i < 16; i++) {
        int flat = i * 256 + tid;
        int l = flat >> 6, s = flat & 63;
        float acc = 0.0f;
        #pragma unroll
        for (int e = 0; e < 64; e++)
            acc = fmaf(qs[l * 65 + e], ks[s * 65 + e], acc);
        ss[l * 65 + s] = acc * 0.125f;
    }
    __syncthreads();

    if (tid < 64) {
        int l = tid;
        float mx = -1e30f;
        #pragma unroll
        for (int s = 0; s < 64; s++) mx = fmaxf(mx, ss[l * 65 + s]);
        float sum = 0.0f;
        #pragma unroll
        for (int s = 0; s < 64; s++) {
            float e = expf(ss[l * 65 + s] - mx);
            ss[l * 65 + s] = e;
            sum += e;
        }
        float inv = 1.0f / sum;
        #pragma unroll
        for (int s = 0; s < 64; s++) ss[l * 65 + s] *= inv;
    }
    __syncthreads();

    #pragma unroll
    for (int i = 0; i < 16; i++) {
        int flat = i * 256 + tid;
        int l = flat >> 6, e = flat & 63;
        float acc = 0.0f;
        #pragma unroll
        for (int s = 0; s < 64; s++)
            acc = fmaf(ss[l * 65 + s], vs[s * 65 + e], acc);
        g_attn[((size_t)bc * 64 + l) * D_ + h * 64 + e] = acc;
    }
}

// ---------------- LayerNorm (row of 512) ----------------
__global__ void ln_kernel(const float* __restrict__ X,
                          const float* __restrict__ g, const float* __restrict__ b,
                          float* __restrict__ Y) {
    int row = blockIdx.x;
    int tid = threadIdx.x;  // 256
    const float* x = X + (size_t)row * D_;
    float v0 = x[tid], v1 = x[tid + 256];
    __shared__ float rs[256], rq[256];
    rs[tid] = v0 + v1;
    rq[tid] = v0 * v0 + v1 * v1;
    __syncthreads();
    for (int off = 128; off > 0; off >>= 1) {
        if (tid < off) { rs[tid] += rs[tid + off]; rq[tid] += rq[tid + off]; }
        __syncthreads();
    }
    __shared__ float s_mean, s_inv;
    if (tid == 0) {
        float mean = rs[0] / (float)D_;
        float var  = rq[0] / (float)D_ - mean * mean;
        s_mean = mean;
        s_inv  = rsqrtf(var + 1e-5f);
    }
    __syncthreads();
    float mean = s_mean, inv = s_inv;
    Y[(size_t)row * D_ + tid]       = (v0 - mean) * inv * g[tid]       + b[tid];
    Y[(size_t)row * D_ + tid + 256] = (v1 - mean) * inv * g[tid + 256] + b[tid + 256];
}

// ---------------- BatchNorm stats (deterministic 2-stage) ----------------
__global__ void bn_partial_kernel() {
    int blk = blockIdx.x;     // 256 blocks * 256 rows
    int d = threadIdx.x;      // 512
    float s = 0.0f, q = 0.0f;
    const float* base = g_tok + (size_t)blk * 256 * D_ + d;
    for (int r = 0; r < 256; r++) {
        float v = base[(size_t)r * D_];
        s += v; q += v * v;
    }
    g_psum[blk * D_ + d] = s;
    g_psq [blk * D_ + d] = q;
}

__global__ void bn_final_kernel(const float* __restrict__ gam,
                                const float* __restrict__ bet) {
    int d = threadIdx.x;      // 512, one block
    float s = 0.0f, q = 0.0f;
    for (int i = 0; i < 256; i++) {
        s += g_psum[i * D_ + d];
        q += g_psq [i * D_ + d];
    }
    float mean = s / (float)ROWS_;
    float var  = q / (float)ROWS_ - mean * mean;
    float a = gam[d] * rsqrtf(var + 1e-5f);
    g_bna[d] = a;
    g_bnb[d] = bet[d] - mean * a;
}

// ---------------- BN apply + (N,D)->(D,N) transpose into enc ----------------
__global__ void enc_transpose_kernel() {
    __shared__ float sm[32][33];
    int bid = blockIdx.x;
    int bc = bid >> 5;
    int r = bid & 31;
    int dt = r >> 1, nt = r & 1;
    int tx = threadIdx.x, ty = threadIdx.y;   // 32 x 8
    int d0 = dt * 32, n0 = nt * 32;
    #pragma unroll
    for (int j = 0; j < 32; j += 8) {
        int n = n0 + ty + j;
        int d = d0 + tx;
        float v = g_tok[((size_t)bc * 64 + n) * D_ + d];
        sm[ty + j][tx] = v * g_bna[d] + g_bnb[d];
    }
    __syncthreads();
    #pragma unroll
    for (int j = 0; j < 32; j += 8) {
        int d = d0 + ty + j;
        int n = n0 + tx;
        g_enc[(size_t)bc * (D_ * N_) + d * N_ + n] = sm[tx][ty + j];
    }
}

// ---------------- head final: sum split-K partials + bias + denorm ----------------
__global__ void head_final_kernel(const float* __restrict__ b_head,
                                  float* __restrict__ out) {
    int m = blockIdx.x;        // bc
    int t = threadIdx.x;       // 512
    float v = b_head[t];
    #pragma unroll
    for (int z = 0; z < KSPLIT_; z++)
        v += g_hpart[((size_t)z * BC_ + m) * T_ + t];
    int b = m >> 5, c = m & 31;
    out[((size_t)b * T_ + t) * C_ + c] = v * g_std[m] + g_mean[m];
}

// ---------------- Launch ----------------
extern "C" void kernel_launch(void* const* d_in, const int* in_sizes, int n_in,
                              void* d_out, int out_size) {
    const float* x_enc = (const float*)d_in[0];
    const float* W_val = (const float*)d_in[1];
    const float* Wq    = (const float*)d_in[2];
    const float* bq    = (const float*)d_in[3];
    const float* Wk    = (const float*)d_in[4];
    const float* bk    = (const float*)d_in[5];
    const float* Wv    = (const float*)d_in[6];
    const float* bv    = (const float*)d_in[7];
    const float* Wo    = (const float*)d_in[8];
    const float* bo    = (const float*)d_in[9];
    const float* Wc1   = (const float*)d_in[10];
    const float* bc1   = (const float*)d_in[11];
    const float* Wc2   = (const float*)d_in[12];
    const float* bc2   = (const float*)d_in[13];
    const float* ln1_g = (const float*)d_in[14];
    const float* ln1_b = (const float*)d_in[15];
    const float* ln2_g = (const float*)d_in[16];
    const float* ln2_b = (const float*)d_in[17];
    const float* bn_g  = (const float*)d_in[18];
    const float* bn_b  = (const float*)d_in[19];
    const float* W_head= (const float*)d_in[20];
    const float* b_head= (const float*)d_in[21];
    float* out = (float*)d_out;

    float *tok, *q, *k, *v, *attn, *y, *h, *enc, *hpart;
    cudaGetSymbolAddress((void**)&tok,   g_tok);
    cudaGetSymbolAddress((void**)&q,     g_q);
    cudaGetSymbolAddress((void**)&k,     g_k);
    cudaGetSymbolAddress((void**)&v,     g_v);
    cudaGetSymbolAddress((void**)&attn,  g_attn);
    cudaGetSymbolAddress((void**)&y,     g_y);
    cudaGetSymbolAddress((void**)&h,     g_h);
    cudaGetSymbolAddress((void**)&enc,   g_enc);
    cudaGetSymbolAddress((void**)&hpart, g_hpart);

    cudaFuncSetAttribute(attn_kernel, cudaFuncAttributeMaxDynamicSharedMemorySize, ATTN_SMEM);

    inst_stats_kernel<<<BC_, 256>>>(x_enc);
    patch_embed_kernel<<<ROWS_, 512>>>(x_enc, W_val);

    dim3 gproj(D_ / 128, ROWS_ / 128);      // (4, 512)
    dim3 gff1(DFF_ / 128, ROWS_ / 128);     // (16, 512)
    dim3 ghead(T_ / 128, BC_ / 128, KSPLIT_); // (4, 8, 4)

    for (int i = 0; i < NL_; i++) {
        const float* Wq_i  = Wq  + (size_t)i * D_ * D_;
        const float* Wk_i  = Wk  + (size_t)i * D_ * D_;
        const float* Wv_i  = Wv  + (size_t)i * D_ * D_;
        const float* Wo_i  = Wo  + (size_t)i * D_ * D_;
        const float* Wc1_i = Wc1 + (size_t)i * D_ * DFF_;
        const float* Wc2_i = Wc2 + (size_t)i * DFF_ * D_;

        tgemm_kernel<0><<<gproj, 256>>>(tok, Wq_i, bq + i * D_, nullptr, q, ROWS_, D_, D_, D_, D_);
        tgemm_kernel<0><<<gproj, 256>>>(tok, Wk_i, bk + i * D_, nullptr, k, ROWS_, D_, D_, D_, D_);
        tgemm_kernel<0><<<gproj, 256>>>(tok, Wv_i, bv + i * D_, nullptr, v, ROWS_, D_, D_, D_, D_);
        attn_kernel<<<BC_ * H_, 256, ATTN_SMEM>>>();
        tgemm_kernel<1><<<gproj, 256>>>(attn, Wo_i, bo + i * D_, tok, tok, ROWS_, D_, D_, D_, D_);
        ln_kernel<<<ROWS_, 256>>>(tok, ln1_g + i * D_, ln1_b + i * D_, y);
        tgemm_kernel<2><<<gff1, 256>>>(y, Wc1_i, bc1 + i * DFF_, nullptr, h, ROWS_, DFF_, D_, D_, DFF_);
        tgemm_kernel<1><<<gproj, 256>>>(h, Wc2_i, bc2 + i * D_, tok, tok, ROWS_, D_, DFF_, DFF_, D_);
        ln_kernel<<<ROWS_, 256>>>(tok, ln2_g + i * D_, ln2_b + i * D_, tok);
    }

    bn_partial_kernel<<<256, 512>>>();
    bn_final_kernel<<<1, 512>>>(bn_g, bn_b);
    enc_transpose_kernel<<<BC_ * 32, dim3(32, 8)>>>();
    tgemm_kernel<4><<<ghead, 256>>>(enc, W_head, nullptr, nullptr, hpart,
                                    BC_, T_, KCH_, D_ * N_, T_);
    head_final_kernel<<<BC_, T_>>>(b_head, out);
}

// round 4
// speedup vs baseline: 3.2939x; 1.1626x over previous
#include <cuda_runtime.h>
#include <math.h>
#include <stdint.h>

// ---------------- Problem constants ----------------
#define B_    32
#define T_    512
#define C_    32
#define D_    512
#define H_    8
#define E_    64
#define DFF_  2048
#define NL_   3
#define P_    16
#define N_    64
#define BC_   (B_*C_)          // 1024
#define ROWS_ ((BC_)*(N_))     // 65536
#define KSPLIT_ 4
#define KCH_    8192           // 32768 / 4
#define KHEAD_  (D_*N_)        // 32768

// ---------------- Scratch (device globals; no allocation) ----------------
__device__ float g_mean[BC_];
__device__ float g_std[BC_];
__device__ float g_tok  [ROWS_ * D_];
__device__ float g_tokr [ROWS_ * D_];
__device__ float g_q    [ROWS_ * D_];
__device__ float g_k    [ROWS_ * D_];
__device__ float g_v    [ROWS_ * D_];
__device__ float g_attn [ROWS_ * D_];
__device__ float g_y    [ROWS_ * D_];
__device__ float g_h    [ROWS_ * DFF_];
__device__ float g_enc  [BC_ * KHEAD_];
__device__ float g_hpart[KSPLIT_ * BC_ * T_];
__device__ float g_psum [256 * D_];
__device__ float g_psq  [256 * D_];
__device__ float g_bna  [D_];
__device__ float g_bnb  [D_];
// transposed + tf32-rounded + k-pair-permuted weights ([N,K] K-major)
__device__ float g_wqT [NL_ * D_ * D_];
__device__ float g_wkT [NL_ * D_ * D_];
__device__ float g_wvT [NL_ * D_ * D_];
__device__ float g_woT [NL_ * D_ * D_];
__device__ float g_wc1T[NL_ * DFF_ * D_];   // [DFF rows][D cols]
__device__ float g_wc2T[NL_ * D_ * DFF_];   // [D rows][DFF cols]
__device__ float g_whT [T_ * KHEAD_];       // [512 rows][32768 cols]

// ---------------- helpers ----------------
__device__ __forceinline__ uint32_t f2tf32(float f) {
    uint32_t u;
    asm("cvt.rna.tf32.f32 %0, %1;" : "=r"(u) : "f"(f));
    return u;
}
__device__ __forceinline__ float tf32r(float f) { return __uint_as_float(f2tf32(f)); }

#define CP16(dst, src)  asm volatile("cp.async.cg.shared.global [%0], [%1], 16;\n" :: "r"(dst), "l"(src))
#define CP_COMMIT()     asm volatile("cp.async.commit_group;\n")
#define CP_WAIT1()      asm volatile("cp.async.wait_group 1;\n")
#define CP_WAIT0()      asm volatile("cp.async.wait_group 0;\n")

__device__ __forceinline__ uint32_t smem_u32(const void* p) {
    uint32_t a;
    asm("{ .reg .u64 t; cvta.to.shared.u64 t, %1; cvt.u32.u64 %0, t; }" : "=r"(a) : "l"(p));
    return a;
}

// ---------------- Weight transpose + tf32 round + k-pair permute ----------------
// Output layout: WT[n][pos(k)] where within each 8-group pos interleaves so
// (k, k+4) land adjacent: pos = (k & ~7) | ((k&3)<<1) | ((k>>2)&1).
__global__ void wtrans_kernel(const float* __restrict__ W, float* __restrict__ WT,
                              int K, int N) {
    __shared__ float s[32][33];
    int n0 = blockIdx.x * 32, k0 = blockIdx.y * 32;
    int tx = threadIdx.x, ty = threadIdx.y;   // 32 x 8
    #pragma unroll
    for (int j = 0; j < 32; j += 8)
        s[ty + j][tx] = W[(size_t)(k0 + ty + j) * N + n0 + tx];
    __syncthreads();
    #pragma unroll
    for (int j = 0; j < 32; j += 8) {
        int k = k0 + tx;
        int pk = (k & ~7) | ((k & 3) << 1) | ((k >> 2) & 1);
        WT[(size_t)(n0 + ty + j) * K + pk] = tf32r(s[tx][ty + j]);
    }
}

// ---------------- Instance-norm stats over time ----------------
__global__ void inst_stats_kernel(const float* __restrict__ x_enc) {
    int bc = blockIdx.x;
    int b = bc >> 5, c = bc & 31;
    int tid = threadIdx.x;          // 256
    const float* p = x_enc + (size_t)b * T_ * C_ + c;
    float v0 = p[(size_t)tid * C_];
    float v1 = p[(size_t)(tid + 256) * C_];
    float s = v0 + v1, q = v0 * v0 + v1 * v1;
    __shared__ float rs[256], rq[256];
    rs[tid] = s; rq[tid] = q;
    __syncthreads();
    for (int off = 128; off > 0; off >>= 1) {
        if (tid < off) { rs[tid] += rs[tid + off]; rq[tid] += rq[tid + off]; }
        __syncthreads();
    }
    if (tid == 0) {
        float mean = rs[0] / (float)T_;
        float var  = rq[0] / (float)T_ - mean * mean;
        g_mean[bc] = mean;
        g_std[bc]  = sqrtf(var + 1e-5f);
    }
}

// ---------------- Patch embedding + sinusoidal PE ----------------
__global__ void patch_embed_kernel(const float* __restrict__ x_enc,
                                   const float* __restrict__ W_val) {
    int bn = blockIdx.x;            // bc*64 + n
    int bc = bn >> 6, n = bn & 63;
    int b = bc >> 5, c = bc & 31;
    int d = threadIdx.x;            // 512
    __shared__ float pv[P_];
    if (d < P_) {
        int t = n * 8 + d;
        if (t > T_ - 1) t = T_ - 1;
        pv[d] = (x_enc[(size_t)(b * T_ + t) * C_ + c] - g_mean[bc]) / g_std[bc];
    }
    __syncthreads();
    int i2 = d >> 1;
    float div = expf(-(float)(2 * i2) * (logf(10000.0f) / (float)D_));
    float ang = (float)n * div;
    float acc = (d & 1) ? cosf(ang) : sinf(ang);
    #pragma unroll
    for (int p = 0; p < P_; p++)
        acc = fmaf(pv[p], W_val[p * D_ + d], acc);
    g_tok [(size_t)bn * D_ + d] = acc;
    g_tokr[(size_t)bn * D_ + d] = tf32r(acc);
}

// ---------------- TF32 mma.sync GEMM, pre-rounded operands ----------------
// A: [M,K] row-major fp32 (already tf32-RNA-rounded values)
// BT: [N,K] row-major, tf32-rounded, k-pairs permuted within 8-groups
// EPI 0: C = A*B + bias
// EPI 1: C = A*B + bias + res
// EPI 2: C = tf32r(gelu(A*B + bias))
// EPI 4: C = A*B  (split-K partials over blockIdx.z)
#define NSTG   3
#define APITCH 20
#define BPITCH 24
#define ABYTES (128 * APITCH * 4)    // 10240
#define BBYTES (128 * BPITCH * 4)    // 12288
#define STGB   (ABYTES + BBYTES)     // 22528
#define TG_SMEM (NSTG * STGB)        // 67584

template<int EPI>
__global__ __launch_bounds__(256, 2)
void tgemm_kernel(const float* __restrict__ A, const float* __restrict__ BT,
                  const float* __restrict__ bias, const float* __restrict__ res,
                  float* __restrict__ C, int M, int N, int K, int lda, int ldb) {
    extern __shared__ float smf[];
    const uint32_t sbase = smem_u32(smf);

    if (EPI == 4) {
        size_t z = blockIdx.z;
        A  += z * KCH_;
        BT += z * KCH_;
        C  += z * (size_t)M * N;
    }

    const int tid  = threadIdx.x;
    const int warp = tid >> 5, lane = tid & 31;
    const int wm = warp >> 1, wn = warp & 1;       // 4x2 warp grid
    const int lr = lane >> 2, lc = lane & 3;
    const int bm = blockIdx.y * 128, bn = blockIdx.x * 128;

    float acc[2][8][4];
    #pragma unroll
    for (int mt = 0; mt < 2; mt++)
        #pragma unroll
        for (int nt = 0; nt < 8; nt++)
            #pragma unroll
            for (int i = 0; i < 4; i++) acc[mt][nt][i] = 0.0f;

    // copy slots: 2 A-chunks + 2 B-chunks of 16B per thread (tile 128x16 each)
    int arw[2], acx[2];
    const float* pa[2];
    const float* pb[2];
    uint32_t aoff[2], boff[2];
    #pragma unroll
    for (int j = 0; j < 2; j++) {
        int q = tid + j * 256;
        arw[j] = q >> 2; acx[j] = q & 3;
        pa[j] = A  + (size_t)(bm + arw[j]) * lda + acx[j] * 4;
        pb[j] = BT + (size_t)(bn + arw[j]) * ldb + acx[j] * 4;
        aoff[j] = (uint32_t)(arw[j] * (APITCH * 4) + acx[j] * 16);
        boff[j] = (uint32_t)(arw[j] * (BPITCH * 4) + acx[j] * 16);
    }

    const int NIT = K >> 4;

    auto FILL = [&](int s, int k0) {
        uint32_t ab = sbase + s * STGB;
        uint32_t bb = ab + ABYTES;
        #pragma unroll
        for (int j = 0; j < 2; j++) {
            CP16(ab + aoff[j], pa[j] + k0);
            CP16(bb + boff[j], pb[j] + k0);
        }
        CP_COMMIT();
    };

    FILL(0, 0);
    if (NIT > 1) FILL(1, 16); else CP_COMMIT();

    // fragment base indices (in floats)
    const int a0 = (wm * 32 + lr) * APITCH + lc;
    const int b0 = (wn * 64 + lr) * BPITCH + 2 * lc;

    for (int it = 0; it < NIT; ++it) {
        const int s = it % NSTG;
        if (it + 1 < NIT) { CP_WAIT1(); } else { CP_WAIT0(); }
        __syncthreads();
        if (it + 2 < NIT) FILL((it + 2) % NSTG, (it + 2) << 4);

        const float* As = smf + (s * STGB >> 2);
        const float* Bs = As + (ABYTES >> 2);

        #pragma unroll
        for (int ks = 0; ks < 2; ks++) {
            const int kb = ks * 8;
            uint32_t af[2][4];
            #pragma unroll
            for (int mt = 0; mt < 2; mt++) {
                int ab = a0 + mt * (16 * APITCH) + kb;
                af[mt][0] = __float_as_uint(As[ab]);
                af[mt][1] = __float_as_uint(As[ab + 8 * APITCH]);
                af[mt][2] = __float_as_uint(As[ab + 4]);
                af[mt][3] = __float_as_uint(As[ab + 8 * APITCH + 4]);
            }
            uint32_t bf[8][2];
            #pragma unroll
            for (int nt = 0; nt < 8; nt++) {
                const float2 b2 = *(const float2*)&Bs[b0 + nt * (8 * BPITCH) + kb];
                bf[nt][0] = __float_as_uint(b2.x);
                bf[nt][1] = __float_as_uint(b2.y);
            }
            #pragma unroll
            for (int mt = 0; mt < 2; mt++)
                #pragma unroll
                for (int nt = 0; nt < 8; nt++)
                    asm volatile(
                        "mma.sync.aligned.m16n8k8.row.col.f32.tf32.tf32.f32 "
                        "{%0,%1,%2,%3},{%4,%5,%6,%7},{%8,%9},{%0,%1,%2,%3};"
                        : "+f"(acc[mt][nt][0]), "+f"(acc[mt][nt][1]),
                          "+f"(acc[mt][nt][2]), "+f"(acc[mt][nt][3])
                        : "r"(af[mt][0]), "r"(af[mt][1]),
                          "r"(af[mt][2]), "r"(af[mt][3]),
                          "r"(bf[nt][0]), "r"(bf[nt][1]));
        }
        __syncthreads();
    }

    // ---------------- epilogue ----------------
    #pragma unroll
    for (int mt = 0; mt < 2; mt++) {
        #pragma unroll
        for (int half = 0; half < 2; half++) {       // row, row+8
            int m = bm + wm * 32 + mt * 16 + lr + half * 8;
            #pragma unroll
            for (int nt = 0; nt < 8; nt++) {
                int col = bn + wn * 64 + nt * 8 + lc * 2;
                float v0 = acc[mt][nt][half * 2 + 0];
                float v1 = acc[mt][nt][half * 2 + 1];
                if (EPI != 4) { v0 += bias[col]; v1 += bias[col + 1]; }
                if (EPI == 1) {
                    const float2 r2 = *(const float2*)(res + (size_t)m * N + col);
                    v0 += r2.x; v1 += r2.y;
                }
                if (EPI == 2) {
                    v0 = 0.5f * v0 * (1.0f + erff(v0 * 0.70710678118654752f));
                    v1 = 0.5f * v1 * (1.0f + erff(v1 * 0.70710678118654752f));
                    v0 = tf32r(v0); v1 = tf32r(v1);
                }
                *(float2*)(C + (size_t)m * N + col) = make_float2(v0, v1);
            }
        }
    }
}

// ---------------- Attention (per bc, per head); rounded output ----------------
#define ATTN_SMEM (4 * 64 * 65 * 4)
__global__ void attn_kernel() {
    int bh = blockIdx.x;
    int bc = bh >> 3, h = bh & 7;
    extern __shared__ float sm[];
    float* qs = sm;
    float* ks = qs + 64 * 65;
    float* vs = ks + 64 * 65;
    float* ss = vs + 64 * 65;
    int tid = threadIdx.x;   // 256
    const float* Qb = g_q + (size_t)bc * 64 * D_ + h * 64;
    const float* Kb = g_k + (size_t)bc * 64 * D_ + h * 64;
    const float* Vb = g_v + (size_t)bc * 64 * D_ + h * 64;

    #pragma unroll
    for (int i = 0; i < 16; i++) {
        int flat = i * 256 + tid;
        int l = flat >> 6, e = flat & 63;
        qs[l * 65 + e] = Qb[(size_t)l * D_ + e];
        ks[l * 65 + e] = Kb[(size_t)l * D_ + e];
        vs[l * 65 + e] = Vb[(size_t)l * D_ + e];
    }
    __syncthreads();

    #pragma unroll
    for (int i = 0; i < 16; i++) {
        int flat = i * 256 + tid;
        int l = flat >> 6, s = flat & 63;
        float acc = 0.0f;
        #pragma unroll
        for (int e = 0; e < 64; e++)
            acc = fmaf(qs[l * 65 + e], ks[s * 65 + e], acc);
        ss[l * 65 + s] = acc * 0.125f;
    }
    __syncthreads();

    if (tid < 64) {
        int l = tid;
        float mx = -1e30f;
        #pragma unroll
        for (int s = 0; s < 64; s++) mx = fmaxf(mx, ss[l * 65 + s]);
        float sum = 0.0f;
        #pragma unroll
        for (int s = 0; s < 64; s++) {
            float e = expf(ss[l * 65 + s] - mx);
            ss[l * 65 + s] = e;
            sum += e;
        }
        float inv = 1.0f / sum;
        #pragma unroll
        for (int s = 0; s < 64; s++) ss[l * 65 + s] *= inv;
    }
    __syncthreads();

    #pragma unroll
    for (int i = 0; i < 16; i++) {
        int flat = i * 256 + tid;
        int l = flat >> 6, e = flat & 63;
        float acc = 0.0f;
        #pragma unroll
        for (int s = 0; s < 64; s++)
            acc = fmaf(ss[l * 65 + s], vs[s * 65 + e], acc);
        g_attn[((size_t)bc * 64 + l) * D_ + h * 64 + e] = tf32r(acc);
    }
}

// ---------------- LayerNorm (row of 512); optional rounding / extra rounded copy ----------------
__global__ void ln_kernel(const float* __restrict__ X,
                          const float* __restrict__ g, const float* __restrict__ b,
                          float* __restrict__ Y, float* __restrict__ Yr, int roundY) {
    int row = blockIdx.x;
    int tid = threadIdx.x;  // 256
    const float* x = X + (size_t)row * D_;
    float v0 = x[tid], v1 = x[tid + 256];
    __shared__ float rs[256], rq[256];
    rs[tid] = v0 + v1;
    rq[tid] = v0 * v0 + v1 * v1;
    __syncthreads();
    for (int off = 128; off > 0; off >>= 1) {
        if (tid < off) { rs[tid] += rs[tid + off]; rq[tid] += rq[tid + off]; }
        __syncthreads();
    }
    __shared__ float s_mean, s_inv;
    if (tid == 0) {
        float mean = rs[0] / (float)D_;
        float var  = rq[0] / (float)D_ - mean * mean;
        s_mean = mean;
        s_inv  = rsqrtf(var + 1e-5f);
    }
    __syncthreads();
    float mean = s_mean, inv = s_inv;
    float o0 = (v0 - mean) * inv * g[tid]       + b[tid];
    float o1 = (v1 - mean) * inv * g[tid + 256] + b[tid + 256];
    if (roundY) { o0 = tf32r(o0); o1 = tf32r(o1); }
    Y[(size_t)row * D_ + tid]       = o0;
    Y[(size_t)row * D_ + tid + 256] = o1;
    if (Yr) {
        Yr[(size_t)row * D_ + tid]       = tf32r(o0);
        Yr[(size_t)row * D_ + tid + 256] = tf32r(o1);
    }
}

// ---------------- BatchNorm stats (deterministic 2-stage) ----------------
__global__ void bn_partial_kernel() {
    int blk = blockIdx.x;
    int d = threadIdx.x;      // 512
    float s = 0.0f, q = 0.0f;
    const float* base = g_tok + (size_t)blk * 256 * D_ + d;
    for (int r = 0; r < 256; r++) {
        float v = base[(size_t)r * D_];
        s += v; q += v * v;
    }
    g_psum[blk * D_ + d] = s;
    g_psq [blk * D_ + d] = q;
}

__global__ void bn_final_kernel(const float* __restrict__ gam,
                                const float* __restrict__ bet) {
    int d = threadIdx.x;      // 512, one block
    float s = 0.0f, q = 0.0f;
    for (int i = 0; i < 256; i++) {
        s += g_psum[i * D_ + d];
        q += g_psq [i * D_ + d];
    }
    float mean = s / (float)ROWS_;
    float var  = q / (float)ROWS_ - mean * mean;
    float a = gam[d] * rsqrtf(var + 1e-5f);
    g_bna[d] = a;
    g_bnb[d] = bet[d] - mean * a;
}

// ---------------- BN apply + (N,D)->(D,N) transpose into enc (rounded) ----------------
__global__ void enc_transpose_kernel() {
    __shared__ float sm[32][33];
    int bid = blockIdx.x;
    int bc = bid >> 5;
    int r = bid & 31;
    int dt = r >> 1, nt = r & 1;
    int tx = threadIdx.x, ty = threadIdx.y;   // 32 x 8
    int d0 = dt * 32, n0 = nt * 32;
    #pragma unroll
    for (int j = 0; j < 32; j += 8) {
        int n = n0 + ty + j;
        int d = d0 + tx;
        float v = g_tok[((size_t)bc * 64 + n) * D_ + d];
        sm[ty + j][tx] = v * g_bna[d] + g_bnb[d];
    }
    __syncthreads();
    #pragma unroll
    for (int j = 0; j < 32; j += 8) {
        int d = d0 + ty + j;
        int n = n0 + tx;
        g_enc[(size_t)bc * KHEAD_ + d * N_ + n] = tf32r(sm[tx][ty + j]);
    }
}

// ---------------- head final: sum split-K partials + bias + denorm ----------------
__global__ void head_final_kernel(const float* __restrict__ b_head,
                                  float* __restrict__ out) {
    int m = blockIdx.x;        // bc
    int t = threadIdx.x;       // 512
    float v = b_head[t];
    #pragma unroll
    for (int z = 0; z < KSPLIT_; z++)
        v += g_hpart[((size_t)z * BC_ + m) * T_ + t];
    int b = m >> 5, c = m & 31;
    out[((size_t)b * T_ + t) * C_ + c] = v * g_std[m] + g_mean[m];
}

// ---------------- Launch ----------------
extern "C" void kernel_launch(void* const* d_in, const int* in_sizes, int n_in,
                              void* d_out, int out_size) {
    const float* x_enc = (const float*)d_in[0];
    const float* W_val = (const float*)d_in[1];
    const float* Wq    = (const float*)d_in[2];
    const float* bq    = (const float*)d_in[3];
    const float* Wk    = (const float*)d_in[4];
    const float* bk    = (const float*)d_in[5];
    const float* Wv    = (const float*)d_in[6];
    const float* bv    = (const float*)d_in[7];
    const float* Wo    = (const float*)d_in[8];
    const float* bo    = (const float*)d_in[9];
    const float* Wc1   = (const float*)d_in[10];
    const float* bc1   = (const float*)d_in[11];
    const float* Wc2   = (const float*)d_in[12];
    const float* bc2   = (const float*)d_in[13];
    const float* ln1_g = (const float*)d_in[14];
    const float* ln1_b = (const float*)d_in[15];
    const float* ln2_g = (const float*)d_in[16];
    const float* ln2_b = (const float*)d_in[17];
    const float* bn_g  = (const float*)d_in[18];
    const float* bn_b  = (const float*)d_in[19];
    const float* W_head= (const float*)d_in[20];
    const float* b_head= (const float*)d_in[21];
    float* out = (float*)d_out;

    float *tok, *tokr, *q, *k, *v, *attn, *y, *h, *enc, *hpart;
    float *wqT, *wkT, *wvT, *woT, *wc1T, *wc2T, *whT;
    cudaGetSymbolAddress((void**)&tok,   g_tok);
    cudaGetSymbolAddress((void**)&tokr,  g_tokr);
    cudaGetSymbolAddress((void**)&q,     g_q);
    cudaGetSymbolAddress((void**)&k,     g_k);
    cudaGetSymbolAddress((void**)&v,     g_v);
    cudaGetSymbolAddress((void**)&attn,  g_attn);
    cudaGetSymbolAddress((void**)&y,     g_y);
    cudaGetSymbolAddress((void**)&h,     g_h);
    cudaGetSymbolAddress((void**)&enc,   g_enc);
    cudaGetSymbolAddress((void**)&hpart, g_hpart);
    cudaGetSymbolAddress((void**)&wqT,   g_wqT);
    cudaGetSymbolAddress((void**)&wkT,   g_wkT);
    cudaGetSymbolAddress((void**)&wvT,   g_wvT);
    cudaGetSymbolAddress((void**)&woT,   g_woT);
    cudaGetSymbolAddress((void**)&wc1T,  g_wc1T);
    cudaGetSymbolAddress((void**)&wc2T,  g_wc2T);
    cudaGetSymbolAddress((void**)&whT,   g_whT);

    cudaFuncSetAttribute(attn_kernel, cudaFuncAttributeMaxDynamicSharedMemorySize, ATTN_SMEM);
    cudaFuncSetAttribute(tgemm_kernel<0>, cudaFuncAttributeMaxDynamicSharedMemorySize, TG_SMEM);
    cudaFuncSetAttribute(tgemm_kernel<1>, cudaFuncAttributeMaxDynamicSharedMemorySize, TG_SMEM);
    cudaFuncSetAttribute(tgemm_kernel<2>, cudaFuncAttributeMaxDynamicSharedMemorySize, TG_SMEM);
    cudaFuncSetAttribute(tgemm_kernel<4>, cudaFuncAttributeMaxDynamicSharedMemorySize, TG_SMEM);

    // ---- weight transposes + tf32 rounding + k-pair permutation ----
    dim3 tb32(32, 8);
    for (int i = 0; i < NL_; i++) {
        size_t woff = (size_t)i * D_ * D_;
        wtrans_kernel<<<dim3(16, 16), tb32>>>(Wq + woff, wqT + woff, D_, D_);
        wtrans_kernel<<<dim3(16, 16), tb32>>>(Wk + woff, wkT + woff, D_, D_);
        wtrans_kernel<<<dim3(16, 16), tb32>>>(Wv + woff, wvT + woff, D_, D_);
        wtrans_kernel<<<dim3(16, 16), tb32>>>(Wo + woff, woT + woff, D_, D_);
        wtrans_kernel<<<dim3(64, 16), tb32>>>(Wc1 + (size_t)i * D_ * DFF_,
                                              wc1T + (size_t)i * DFF_ * D_, D_, DFF_);
        wtrans_kernel<<<dim3(16, 64), tb32>>>(Wc2 + (size_t)i * DFF_ * D_,
                                              wc2T + (size_t)i * D_ * DFF_, DFF_, D_);
    }
    wtrans_kernel<<<dim3(16, 1024), tb32>>>(W_head, whT, KHEAD_, T_);

    inst_stats_kernel<<<BC_, 256>>>(x_enc);
    patch_embed_kernel<<<ROWS_, 512>>>(x_enc, W_val);

    dim3 gproj(D_ / 128, ROWS_ / 128);        // (4, 512)
    dim3 gff1(DFF_ / 128, ROWS_ / 128);       // (16, 512)
    dim3 ghead(T_ / 128, BC_ / 128, KSPLIT_); // (4, 8, 4)

    for (int i = 0; i < NL_; i++) {
        size_t woff = (size_t)i * D_ * D_;
        tgemm_kernel<0><<<gproj, 256, TG_SMEM>>>(tokr, wqT + woff, bq + i * D_, nullptr, q, ROWS_, D_, D_, D_, D_);
        tgemm_kernel<0><<<gproj, 256, TG_SMEM>>>(tokr, wkT + woff, bk + i * D_, nullptr, k, ROWS_, D_, D_, D_, D_);
        tgemm_kernel<0><<<gproj, 256, TG_SMEM>>>(tokr, wvT + woff, bv + i * D_, nullptr, v, ROWS_, D_, D_, D_, D_);
        attn_kernel<<<BC_ * H_, 256, ATTN_SMEM>>>();
        tgemm_kernel<1><<<gproj, 256, TG_SMEM>>>(attn, woT + woff, bo + i * D_, tok, tok, ROWS_, D_, D_, D_, D_);
        ln_kernel<<<ROWS_, 256>>>(tok, ln1_g + i * D_, ln1_b + i * D_, y, nullptr, 1);
        tgemm_kernel<2><<<gff1, 256, TG_SMEM>>>(y, wc1T + (size_t)i * DFF_ * D_, bc1 + i * DFF_, nullptr, h, ROWS_, DFF_, D_, D_, D_);
        tgemm_kernel<1><<<gproj, 256, TG_SMEM>>>(h, wc2T + (size_t)i * D_ * DFF_, bc2 + i * D_, tok, tok, ROWS_, D_, DFF_, DFF_, DFF_);
        ln_kernel<<<ROWS_, 256>>>(tok, ln2_g + i * D_, ln2_b + i * D_, tok, tokr, 0);
    }

    bn_partial_kernel<<<256, 512>>>();
    bn_final_kernel<<<1, 512>>>(bn_g, bn_b);
    enc_transpose_kernel<<<BC_ * 32, dim3(32, 8)>>>();
    tgemm_kernel<4><<<ghead, 256, TG_SMEM>>>(enc, whT, nullptr, nullptr, hpart,
                                             BC_, T_, KCH_, KHEAD_, KHEAD_);
    head_final_kernel<<<BC_, T_>>>(b_head, out);
}

// round 5
// speedup vs baseline: 4.1075x; 1.2470x over previous
#include <cuda_runtime.h>
#include <cuda_fp16.h>
#include <math.h>
#include <stdint.h>

// ---------------- Problem constants ----------------
#define B_    32
#define T_    512
#define C_    32
#define D_    512
#define H_    8
#define E_    64
#define DFF_  2048
#define NL_   3
#define P_    16
#define N_    64
#define BC_   (B_*C_)          // 1024
#define ROWS_ ((BC_)*(N_))     // 65536
#define KSPLIT_ 4
#define KCH_    8192           // 32768 / 4
#define KHEAD_  (D_*N_)        // 32768

// ---------------- Scratch (device globals; no allocation) ----------------
__device__ float  g_mean[BC_];
__device__ float  g_std[BC_];
__device__ float  g_tok  [ROWS_ * D_];        // fp32 residual stream
__device__ __half g_tok_h[ROWS_ * D_];        // half copy (QKV input)
__device__ __half g_qkv_h[ROWS_ * 1536];      // fused QKV output
__device__ __half g_attn_h[ROWS_ * D_];       // attention output (O input)
__device__ __half g_y_h  [ROWS_ * D_];        // ln1 output (FF1 input)
__device__ __half g_h_h  [ROWS_ * DFF_];      // gelu output (FF2 input)
__device__ __half g_enc_h[BC_ * KHEAD_];      // head input
__device__ float  g_hpart[KSPLIT_ * BC_ * T_];
__device__ float  g_psum [256 * D_];
__device__ float  g_psq  [256 * D_];
__device__ float  g_bna  [D_];
__device__ float  g_bnb  [D_];
__device__ float  g_bqkv [NL_ * 1536];
// transposed half weights ([N,K] K-major)
__device__ __half g_wqkvT[NL_ * 1536 * D_];
__device__ __half g_woT  [NL_ * D_ * D_];
__device__ __half g_wc1T [NL_ * DFF_ * D_];
__device__ __half g_wc2T [NL_ * D_ * DFF_];
__device__ __half g_whT  [T_ * KHEAD_];

// ---------------- helpers ----------------
#define CP16(dst, src)  asm volatile("cp.async.cg.shared.global [%0], [%1], 16;\n" :: "r"(dst), "l"(src))
#define CP_COMMIT()     asm volatile("cp.async.commit_group;\n")
#define CP_WAIT1()      asm volatile("cp.async.wait_group 1;\n")
#define CP_WAIT0()      asm volatile("cp.async.wait_group 0;\n")

__device__ __forceinline__ uint32_t smem_u32(const void* p) {
    uint32_t a;
    asm("{ .reg .u64 t; cvta.to.shared.u64 t, %1; cvt.u32.u64 %0, t; }" : "=r"(a) : "l"(p));
    return a;
}

// ---------------- Weight transpose -> half ----------------
__global__ void whtrans_kernel(const float* __restrict__ W, __half* __restrict__ WT,
                               int K, int N) {
    __shared__ float s[32][33];
    int n0 = blockIdx.x * 32, k0 = blockIdx.y * 32;
    int tx = threadIdx.x, ty = threadIdx.y;   // 32 x 8
    #pragma unroll
    for (int j = 0; j < 32; j += 8)
        s[ty + j][tx] = W[(size_t)(k0 + ty + j) * N + n0 + tx];
    __syncthreads();
    #pragma unroll
    for (int j = 0; j < 32; j += 8)
        WT[(size_t)(n0 + ty + j) * K + k0 + tx] = __float2half_rn(s[tx][ty + j]);
}

__global__ void bqkv_kernel(const float* __restrict__ bq, const float* __restrict__ bk,
                            const float* __restrict__ bv) {
    int i = blockIdx.x, t = threadIdx.x;   // NL_ x 512
    g_bqkv[i * 1536 + t]        = bq[i * D_ + t];
    g_bqkv[i * 1536 + 512 + t]  = bk[i * D_ + t];
    g_bqkv[i * 1536 + 1024 + t] = bv[i * D_ + t];
}

// ---------------- Instance-norm stats over time ----------------
__global__ void inst_stats_kernel(const float* __restrict__ x_enc) {
    int bc = blockIdx.x;
    int b = bc >> 5, c = bc & 31;
    int tid = threadIdx.x;          // 256
    const float* p = x_enc + (size_t)b * T_ * C_ + c;
    float v0 = p[(size_t)tid * C_];
    float v1 = p[(size_t)(tid + 256) * C_];
    __shared__ float rs[256], rq[256];
    rs[tid] = v0 + v1; rq[tid] = v0 * v0 + v1 * v1;
    __syncthreads();
    for (int off = 128; off > 0; off >>= 1) {
        if (tid < off) { rs[tid] += rs[tid + off]; rq[tid] += rq[tid + off]; }
        __syncthreads();
    }
    if (tid == 0) {
        float mean = rs[0] / (float)T_;
        float var  = rq[0] / (float)T_ - mean * mean;
        g_mean[bc] = mean;
        g_std[bc]  = sqrtf(var + 1e-5f);
    }
}

// ---------------- Patch embedding + sinusoidal PE ----------------
__global__ void patch_embed_kernel(const float* __restrict__ x_enc,
                                   const float* __restrict__ W_val) {
    int bn = blockIdx.x;            // bc*64 + n
    int bc = bn >> 6, n = bn & 63;
    int b = bc >> 5, c = bc & 31;
    int d = threadIdx.x;            // 512
    __shared__ float pv[P_];
    if (d < P_) {
        int t = n * 8 + d;
        if (t > T_ - 1) t = T_ - 1;
        pv[d] = (x_enc[(size_t)(b * T_ + t) * C_ + c] - g_mean[bc]) / g_std[bc];
    }
    __syncthreads();
    int i2 = d >> 1;
    float div = expf(-(float)(2 * i2) * (logf(10000.0f) / (float)D_));
    float ang = (float)n * div;
    float acc = (d & 1) ? cosf(ang) : sinf(ang);
    #pragma unroll
    for (int p = 0; p < P_; p++)
        acc = fmaf(pv[p], W_val[p * D_ + d], acc);
    g_tok  [(size_t)bn * D_ + d] = acc;
    g_tok_h[(size_t)bn * D_ + d] = __float2half_rn(acc);
}

// ---------------- FP16 mma.sync GEMM (m16n8k16), 128x128x32 tiles ----------------
// A: [M,K] half row-major; BT: [N,K] half row-major (= col-major B)
// EPI 0: Ch = h(A*B + bias)
// EPI 1: Cf = A*B + bias + res      (fp32 out)
// EPI 2: Ch = h(gelu(A*B + bias))
// EPI 4: Cf = A*B   (split-K partials via blockIdx.z)
#define HPITCH 40                    // halves per row (80B, conflict-free)
#define STGH   (2 * 128 * HPITCH)    // 10240 halves per stage (A+B)
#define NSTG   3
#define HG_SMEM (NSTG * STGH * 2)    // 61440 bytes

template<int EPI>
__global__ __launch_bounds__(256, 2)
void hgemm_kernel(const __half* __restrict__ A, const __half* __restrict__ BT,
                  const float* __restrict__ bias, const float* __restrict__ res,
                  void* __restrict__ Cv, int M, int N, int K, int lda, int ldb) {
    extern __shared__ __half smh[];
    const uint32_t sbase = smem_u32(smh);

    if (EPI == 4) {
        size_t z = blockIdx.z;
        A  += z * KCH_;
        BT += z * KCH_;
    }

    const int tid  = threadIdx.x;
    const int warp = tid >> 5, lane = tid & 31;
    const int wm = warp >> 1, wn = warp & 1;       // 4x2 warp grid
    const int lr = lane >> 2, lc = lane & 3;
    const int bm = blockIdx.y * 128, bn = blockIdx.x * 128;

    float acc[2][8][4];
    #pragma unroll
    for (int mt = 0; mt < 2; mt++)
        #pragma unroll
        for (int nt = 0; nt < 8; nt++)
            #pragma unroll
            for (int i = 0; i < 4; i++) acc[mt][nt][i] = 0.0f;

    // copy slots: per thread 2 A-chunks + 2 B-chunks of 16B (tile 128 x 32 halves)
    const __half* pA[2];
    const __half* pB[2];
    uint32_t aof[2], bof[2];
    #pragma unroll
    for (int j = 0; j < 2; j++) {
        int q = tid + j * 256;                 // 0..511
        int row = q >> 2, c16 = q & 3;
        pA[j] = A  + (size_t)(bm + row) * lda + c16 * 8;
        pB[j] = BT + (size_t)(bn + row) * ldb + c16 * 8;
        aof[j] = (uint32_t)(row * (HPITCH * 2) + c16 * 16);
        bof[j] = aof[j];
    }

    const int NIT = K >> 5;

    auto FILL = [&](int s, int k0) {
        uint32_t ab = sbase + s * (STGH * 2);
        uint32_t bb = ab + 128 * HPITCH * 2;
        #pragma unroll
        for (int j = 0; j < 2; j++) {
            CP16(ab + aof[j], pA[j] + k0);
            CP16(bb + bof[j], pB[j] + k0);
        }
        CP_COMMIT();
    };

    FILL(0, 0);
    FILL(1, 32);

    const int a_base = (wm * 32 + lr) * HPITCH + 2 * lc;
    const int b_base = (wn * 64 + lr) * HPITCH + 2 * lc;

    for (int it = 0; it < NIT; ++it) {
        const int s = it % NSTG;
        if (it + 1 < NIT) { CP_WAIT1(); } else { CP_WAIT0(); }
        __syncthreads();
        if (it + 2 < NIT) FILL((it + 2) % NSTG, (it + 2) << 5);

        const __half* As = smh + s * STGH;
        const __half* Bs = As + 128 * HPITCH;

        #pragma unroll
        for (int ks = 0; ks < 2; ks++) {
            const int kb = ks * 16;
            uint32_t af[2][4];
            #pragma unroll
            for (int mt = 0; mt < 2; mt++) {
                int ai = a_base + mt * (16 * HPITCH) + kb;
                af[mt][0] = *(const uint32_t*)(As + ai);
                af[mt][1] = *(const uint32_t*)(As + ai + 8 * HPITCH);
                af[mt][2] = *(const uint32_t*)(As + ai + 8);
                af[mt][3] = *(const uint32_t*)(As + ai + 8 * HPITCH + 8);
            }
            uint32_t bf[8][2];
            #pragma unroll
            for (int nt = 0; nt < 8; nt++) {
                int bi = b_base + nt * (8 * HPITCH) + kb;
                bf[nt][0] = *(const uint32_t*)(Bs + bi);
                bf[nt][1] = *(const uint32_t*)(Bs + bi + 8);
            }
            #pragma unroll
            for (int mt = 0; mt < 2; mt++)
                #pragma unroll
                for (int nt = 0; nt < 8; nt++)
                    asm volatile(
                        "mma.sync.aligned.m16n8k16.row.col.f32.f16.f16.f32 "
                        "{%0,%1,%2,%3},{%4,%5,%6,%7},{%8,%9},{%0,%1,%2,%3};"
                        : "+f"(acc[mt][nt][0]), "+f"(acc[mt][nt][1]),
                          "+f"(acc[mt][nt][2]), "+f"(acc[mt][nt][3])
                        : "r"(af[mt][0]), "r"(af[mt][1]),
                          "r"(af[mt][2]), "r"(af[mt][3]),
                          "r"(bf[nt][0]), "r"(bf[nt][1]));
        }
        __syncthreads();
    }

    // ---------------- epilogue ----------------
    float* Cf = (float*)Cv;
    __half* Ch = (__half*)Cv;
    if (EPI == 4) Cf += (size_t)blockIdx.z * M * N;

    #pragma unroll
    for (int mt = 0; mt < 2; mt++) {
        #pragma unroll
        for (int half = 0; half < 2; half++) {
            int m = bm + wm * 32 + mt * 16 + lr + half * 8;
            #pragma unroll
            for (int nt = 0; nt < 8; nt++) {
                int col = bn + wn * 64 + nt * 8 + lc * 2;
                float v0 = acc[mt][nt][half * 2 + 0];
                float v1 = acc[mt][nt][half * 2 + 1];
                if (EPI != 4) { v0 += bias[col]; v1 += bias[col + 1]; }
                if (EPI == 1) {
                    const float2 r2 = *(const float2*)(res + (size_t)m * N + col);
                    v0 += r2.x; v1 += r2.y;
                }
                if (EPI == 2) {
                    v0 = 0.5f * v0 * (1.0f + erff(v0 * 0.70710678118654752f));
                    v1 = 0.5f * v1 * (1.0f + erff(v1 * 0.70710678118654752f));
                }
                if (EPI == 0 || EPI == 2) {
                    __half2 hv;
                    hv.x = __float2half_rn(v0); hv.y = __float2half_rn(v1);
                    *(__half2*)(Ch + (size_t)m * N + col) = hv;
                } else {
                    *(float2*)(Cf + (size_t)m * N + col) = make_float2(v0, v1);
                }
            }
        }
    }
}

// ---------------- Attention (per bc, per head), register-tiled ----------------
// smem: qs[64][68], kt[64][68] (K transposed: kt[e][s]), vs[64][68], ss[64][68]
#define ATTN_SMEM (4 * 64 * 68 * 4)
__global__ void attn_kernel() {
    int bh = blockIdx.x;
    int bc = bh >> 3, h = bh & 7;
    extern __shared__ float sm[];
    float* qs = sm;
    float* kt = qs + 64 * 68;
    float* vs = kt + 64 * 68;
    float* ss = vs + 64 * 68;
    int tid = threadIdx.x;   // 256
    const __half* Qb = g_qkv_h + (size_t)bc * 64 * 1536 + h * 64;
    const __half* Kb = Qb + 512;
    const __half* Vb = Qb + 1024;

    #pragma unroll
    for (int i = 0; i < 16; i++) {
        int flat = i * 256 + tid;
        int r = flat >> 6, e = flat & 63;
        qs[r * 68 + e] = __half2float(Qb[(size_t)r * 1536 + e]);
        kt[e * 68 + r] = __half2float(Kb[(size_t)r * 1536 + e]);   // transpose
        vs[r * 68 + e] = __half2float(Vb[(size_t)r * 1536 + e]);
    }
    __syncthreads();

    const int l  = tid >> 2;
    const int sq = tid & 3;
    const int s0 = sq << 4;

    // ---- scores = Q K^T * scale; softmax in registers ----
    float a[16];
    #pragma unroll
    for (int j = 0; j < 16; j++) a[j] = 0.0f;
    for (int e = 0; e < 64; e++) {
        float qv = qs[l * 68 + e];
        const float* kr = &kt[e * 68 + s0];
        float4 k0 = *(const float4*)(kr);
        float4 k1 = *(const float4*)(kr + 4);
        float4 k2 = *(const float4*)(kr + 8);
        float4 k3 = *(const float4*)(kr + 12);
        a[0]  = fmaf(qv, k0.x, a[0]);  a[1]  = fmaf(qv, k0.y, a[1]);
        a[2]  = fmaf(qv, k0.z, a[2]);  a[3]  = fmaf(qv, k0.w, a[3]);
        a[4]  = fmaf(qv, k1.x, a[4]);  a[5]  = fmaf(qv, k1.y, a[5]);
        a[6]  = fmaf(qv, k1.z, a[6]);  a[7]  = fmaf(qv, k1.w, a[7]);
        a[8]  = fmaf(qv, k2.x, a[8]);  a[9]  = fmaf(qv, k2.y, a[9]);
        a[10] = fmaf(qv, k2.z, a[10]); a[11] = fmaf(qv, k2.w, a[11]);
        a[12] = fmaf(qv, k3.x, a[12]); a[13] = fmaf(qv, k3.y, a[13]);
        a[14] = fmaf(qv, k3.z, a[14]); a[15] = fmaf(qv, k3.w, a[15]);
    }
    float mx = -1e30f;
    #pragma unroll
    for (int j = 0; j < 16; j++) { a[j] *= 0.125f; mx = fmaxf(mx, a[j]); }
    mx = fmaxf(mx, __shfl_xor_sync(0xffffffffu, mx, 1));
    mx = fmaxf(mx, __shfl_xor_sync(0xffffffffu, mx, 2));
    float sum = 0.0f;
    #pragma unroll
    for (int j = 0; j < 16; j++) { a[j] = expf(a[j] - mx); sum += a[j]; }
    sum += __shfl_xor_sync(0xffffffffu, sum, 1);
    sum += __shfl_xor_sync(0xffffffffu, sum, 2);
    float inv = 1.0f / sum;
    #pragma unroll
    for (int j = 0; j < 16; j++) ss[l * 68 + s0 + j] = a[j] * inv;
    __syncthreads();

    // ---- out = A V ----
    const int e0 = s0;   // same 16-wide segment role, now over e
    float o[16];
    #pragma unroll
    for (int j = 0; j < 16; j++) o[j] = 0.0f;
    for (int s = 0; s < 64; s++) {
        float av = ss[l * 68 + s];
        const float* vr = &vs[s * 68 + e0];
        float4 v0 = *(const float4*)(vr);
        float4 v1 = *(const float4*)(vr + 4);
        float4 v2 = *(const float4*)(vr + 8);
        float4 v3 = *(const float4*)(vr + 12);
        o[0]  = fmaf(av, v0.x, o[0]);  o[1]  = fmaf(av, v0.y, o[1]);
        o[2]  = fmaf(av, v0.z, o[2]);  o[3]  = fmaf(av, v0.w, o[3]);
        o[4]  = fmaf(av, v1.x, o[4]);  o[5]  = fmaf(av, v1.y, o[5]);
        o[6]  = fmaf(av, v1.z, o[6]);  o[7]  = fmaf(av, v1.w, o[7]);
        o[8]  = fmaf(av, v2.x, o[8]);  o[9]  = fmaf(av, v2.y, o[9]);
        o[10] = fmaf(av, v2.z, o[10]); o[11] = fmaf(av, v2.w, o[11]);
        o[12] = fmaf(av, v3.x, o[12]); o[13] = fmaf(av, v3.y, o[13]);
        o[14] = fmaf(av, v3.z, o[14]); o[15] = fmaf(av, v3.w, o[15]);
    }
    __half* Ob = g_attn_h + ((size_t)bc * 64 + l) * D_ + h * 64 + e0;
    #pragma unroll
    for (int j = 0; j < 16; j += 2) {
        __half2 hv;
        hv.x = __float2half_rn(o[j]); hv.y = __float2half_rn(o[j + 1]);
        *(__half2*)(Ob + j) = hv;
    }
}

// ---------------- LayerNorm (row of 512) ----------------
__global__ void ln_kernel(const float* __restrict__ X,
                          const float* __restrict__ g, const float* __restrict__ b,
                          float* __restrict__ Yf, __half* __restrict__ Yh) {
    int row = blockIdx.x;
    int tid = threadIdx.x;  // 256
    const float* x = X + (size_t)row * D_;
    float v0 = x[tid], v1 = x[tid + 256];
    __shared__ float rs[256], rq[256];
    rs[tid] = v0 + v1;
    rq[tid] = v0 * v0 + v1 * v1;
    __syncthreads();
    for (int off = 128; off > 0; off >>= 1) {
        if (tid < off) { rs[tid] += rs[tid + off]; rq[tid] += rq[tid + off]; }
        __syncthreads();
    }
    __shared__ float s_mean, s_inv;
    if (tid == 0) {
        float mean = rs[0] / (float)D_;
        float var  = rq[0] / (float)D_ - mean * mean;
        s_mean = mean;
        s_inv  = rsqrtf(var + 1e-5f);
    }
    __syncthreads();
    float mean = s_mean, inv = s_inv;
    float o0 = (v0 - mean) * inv * g[tid]       + b[tid];
    float o1 = (v1 - mean) * inv * g[tid + 256] + b[tid + 256];
    if (Yf) {
        Yf[(size_t)row * D_ + tid]       = o0;
        Yf[(size_t)row * D_ + tid + 256] = o1;
    }
    if (Yh) {
        Yh[(size_t)row * D_ + tid]       = __float2half_rn(o0);
        Yh[(size_t)row * D_ + tid + 256] = __float2half_rn(o1);
    }
}

// ---------------- BatchNorm stats (deterministic 2-stage) ----------------
__global__ void bn_partial_kernel() {
    int blk = blockIdx.x;
    int d = threadIdx.x;      // 512
    float s = 0.0f, q = 0.0f;
    const float* base = g_tok + (size_t)blk * 256 * D_ + d;
    for (int r = 0; r < 256; r++) {
        float v = base[(size_t)r * D_];
        s += v; q += v * v;
    }
    g_psum[blk * D_ + d] = s;
    g_psq [blk * D_ + d] = q;
}

__global__ void bn_final_kernel(const float* __restrict__ gam,
                                const float* __restrict__ bet) {
    int d = threadIdx.x;      // 512, one block
    float s = 0.0f, q = 0.0f;
    for (int i = 0; i < 256; i++) {
        s += g_psum[i * D_ + d];
        q += g_psq [i * D_ + d];
    }
    float mean = s / (float)ROWS_;
    float var  = q / (float)ROWS_ - mean * mean;
    float a = gam[d] * rsqrtf(var + 1e-5f);
    g_bna[d] = a;
    g_bnb[d] = bet[d] - mean * a;
}

// ---------------- BN apply + (N,D)->(D,N) transpose into enc (half) ----------------
__global__ void enc_transpose_kernel() {
    __shared__ float sm[32][33];
    int bid = blockIdx.x;
    int bc = bid >> 5;
    int r = bid & 31;
    int dt = r >> 1, nt = r & 1;
    int tx = threadIdx.x, ty = threadIdx.y;   // 32 x 8
    int d0 = dt * 32, n0 = nt * 32;
    #pragma unroll
    for (int j = 0; j < 32; j += 8) {
        int n = n0 + ty + j;
        int d = d0 + tx;
        float v = g_tok[((size_t)bc * 64 + n) * D_ + d];
        sm[ty + j][tx] = v * g_bna[d] + g_bnb[d];
    }
    __syncthreads();
    #pragma unroll
    for (int j = 0; j < 32; j += 8) {
        int d = d0 + ty + j;
        int n = n0 + tx;
        g_enc_h[(size_t)bc * KHEAD_ + d * N_ + n] = __float2half_rn(sm[tx][ty + j]);
    }
}

// ---------------- head final: sum split-K partials + bias + denorm ----------------
__global__ void head_final_kernel(const float* __restrict__ b_head,
                                  float* __restrict__ out) {
    int m = blockIdx.x;        // bc
    int t = threadIdx.x;       // 512
    float v = b_head[t];
    #pragma unroll
    for (int z = 0; z < KSPLIT_; z++)
        v += g_hpart[((size_t)z * BC_ + m) * T_ + t];
    int b = m >> 5, c = m & 31;
    out[((size_t)b * T_ + t) * C_ + c] = v * g_std[m] + g_mean[m];
}

// ---------------- Launch ----------------
extern "C" void kernel_launch(void* const* d_in, const int* in_sizes, int n_in,
                              void* d_out, int out_size) {
    const float* x_enc = (const float*)d_in[0];
    const float* W_val = (const float*)d_in[1];
    const float* Wq    = (const float*)d_in[2];
    const float* bq    = (const float*)d_in[3];
    const float* Wk    = (const float*)d_in[4];
    const float* bk    = (const float*)d_in[5];
    const float* Wv    = (const float*)d_in[6];
    const float* bv    = (const float*)d_in[7];
    const float* Wo    = (const float*)d_in[8];
    const float* bo    = (const float*)d_in[9];
    const float* Wc1   = (const float*)d_in[10];
    const float* bc1   = (const float*)d_in[11];
    const float* Wc2   = (const float*)d_in[12];
    const float* bc2   = (const float*)d_in[13];
    const float* ln1_g = (const float*)d_in[14];
    const float* ln1_b = (const float*)d_in[15];
    const float* ln2_g = (const float*)d_in[16];
    const float* ln2_b = (const float*)d_in[17];
    const float* bn_g  = (const float*)d_in[18];
    const float* bn_b  = (const float*)d_in[19];
    const float* W_head= (const float*)d_in[20];
    const float* b_head= (const float*)d_in[21];
    float* out = (float*)d_out;

    float *tok, *hpart, *bqkv;
    __half *tok_h, *qkv_h, *attn_h, *y_h, *h_h, *enc_h;
    __half *wqkvT, *woT, *wc1T, *wc2T, *whT;
    cudaGetSymbolAddress((void**)&tok,    g_tok);
    cudaGetSymbolAddress((void**)&tok_h,  g_tok_h);
    cudaGetSymbolAddress((void**)&qkv_h,  g_qkv_h);
    cudaGetSymbolAddress((void**)&attn_h, g_attn_h);
    cudaGetSymbolAddress((void**)&y_h,    g_y_h);
    cudaGetSymbolAddress((void**)&h_h,    g_h_h);
    cudaGetSymbolAddress((void**)&enc_h,  g_enc_h);
    cudaGetSymbolAddress((void**)&hpart,  g_hpart);
    cudaGetSymbolAddress((void**)&bqkv,   g_bqkv);
    cudaGetSymbolAddress((void**)&wqkvT,  g_wqkvT);
    cudaGetSymbolAddress((void**)&woT,    g_woT);
    cudaGetSymbolAddress((void**)&wc1T,   g_wc1T);
    cudaGetSymbolAddress((void**)&wc2T,   g_wc2T);
    cudaGetSymbolAddress((void**)&whT,    g_whT);

    cudaFuncSetAttribute(attn_kernel, cudaFuncAttributeMaxDynamicSharedMemorySize, ATTN_SMEM);
    cudaFuncSetAttribute(hgemm_kernel<0>, cudaFuncAttributeMaxDynamicSharedMemorySize, HG_SMEM);
    cudaFuncSetAttribute(hgemm_kernel<1>, cudaFuncAttributeMaxDynamicSharedMemorySize, HG_SMEM);
    cudaFuncSetAttribute(hgemm_kernel<2>, cudaFuncAttributeMaxDynamicSharedMemorySize, HG_SMEM);
    cudaFuncSetAttribute(hgemm_kernel<4>, cudaFuncAttributeMaxDynamicSharedMemorySize, HG_SMEM);

    // ---- weight prep: transpose -> half ----
    dim3 tb32(32, 8);
    for (int i = 0; i < NL_; i++) {
        whtrans_kernel<<<dim3(16, 16), tb32>>>(Wq + (size_t)i * D_ * D_,
            wqkvT + (size_t)i * 1536 * D_, D_, D_);
        whtrans_kernel<<<dim3(16, 16), tb32>>>(Wk + (size_t)i * D_ * D_,
            wqkvT + (size_t)i * 1536 * D_ + (size_t)512 * D_, D_, D_);
        whtrans_kernel<<<dim3(16, 16), tb32>>>(Wv + (size_t)i * D_ * D_,
            wqkvT + (size_t)i * 1536 * D_ + (size_t)1024 * D_, D_, D_);
        whtrans_kernel<<<dim3(16, 16), tb32>>>(Wo + (size_t)i * D_ * D_,
            woT + (size_t)i * D_ * D_, D_, D_);
        whtrans_kernel<<<dim3(64, 16), tb32>>>(Wc1 + (size_t)i * D_ * DFF_,
            wc1T + (size_t)i * DFF_ * D_, D_, DFF_);
        whtrans_kernel<<<dim3(16, 64), tb32>>>(Wc2 + (size_t)i * DFF_ * D_,
            wc2T + (size_t)i * D_ * DFF_, DFF_, D_);
    }
    whtrans_kernel<<<dim3(16, 1024), tb32>>>(W_head, whT, KHEAD_, T_);
    bqkv_kernel<<<NL_, 512>>>(bq, bk, bv);

    inst_stats_kernel<<<BC_, 256>>>(x_enc);
    patch_embed_kernel<<<ROWS_, 512>>>(x_enc, W_val);

    dim3 gqkv(1536 / 128, ROWS_ / 128);       // (12, 512)
    dim3 gproj(D_ / 128, ROWS_ / 128);        // (4, 512)
    dim3 gff1(DFF_ / 128, ROWS_ / 128);       // (16, 512)
    dim3 ghead(T_ / 128, BC_ / 128, KSPLIT_); // (4, 8, 4)

    for (int i = 0; i < NL_; i++) {
        hgemm_kernel<0><<<gqkv, 256, HG_SMEM>>>(tok_h, wqkvT + (size_t)i * 1536 * D_,
            bqkv + i * 1536, nullptr, qkv_h, ROWS_, 1536, D_, D_, D_);
        attn_kernel<<<BC_ * H_, 256, ATTN_SMEM>>>();
        hgemm_kernel<1><<<gproj, 256, HG_SMEM>>>(attn_h, woT + (size_t)i * D_ * D_,
            bo + i * D_, tok, tok, ROWS_, D_, D_, D_, D_);
        ln_kernel<<<ROWS_, 256>>>(tok, ln1_g + i * D_, ln1_b + i * D_, nullptr, y_h);
        hgemm_kernel<2><<<gff1, 256, HG_SMEM>>>(y_h, wc1T + (size_t)i * DFF_ * D_,
            bc1 + i * DFF_, nullptr, h_h, ROWS_, DFF_, D_, D_, D_);
        hgemm_kernel<1><<<gproj, 256, HG_SMEM>>>(h_h, wc2T + (size_t)i * D_ * DFF_,
            bc2 + i * D_, tok, tok, ROWS_, D_, DFF_, DFF_, DFF_);
        ln_kernel<<<ROWS_, 256>>>(tok, ln2_g + i * D_, ln2_b + i * D_, tok, tok_h);
    }

    bn_partial_kernel<<<256, 512>>>();
    bn_final_kernel<<<1, 512>>>(bn_g, bn_b);
    enc_transpose_kernel<<<BC_ * 32, dim3(32, 8)>>>();
    hgemm_kernel<4><<<ghead, 256, HG_SMEM>>>(enc_h, whT, nullptr, nullptr, hpart,
                                             BC_, T_, KCH_, KHEAD_, KHEAD_);
    head_final_kernel<<<BC_, T_>>>(b_head, out);
}